// round 1
// baseline (speedup 1.0000x reference)
#include <cuda_runtime.h>
#include <math.h>

#define BB 2
#define NN 8192
#define NPT (BB*NN)
#define KNN 10
#define TILE 2048

// ---------------- device scratch (no allocations allowed) ----------------
__device__ float4 g_pts4[NPT];     // x,y,z,sq
__device__ float  g_Tj[NPT];       // mask? T : -inf  (density threshold per column)
__device__ float  g_center[BB][3];
__device__ float  g_masksum[BB];
__device__ float  g_geom[NPT * 6];
__device__ int    g_mtype;         // bit0: nonzero byte at i%4==1 (u8); bit1: nonzero at i%4 in {2,3} (f32)
__device__ float  g_T;             // exact density d2 threshold

// ---------------- init: exact sqrt threshold + flag reset ----------------
__global__ void k_init() {
    g_mtype = 0;
    const float R = 0.02f;
    float t = __fmul_rn(R, R);
    // largest float t with sqrt_rn(t) < R  => (d2 <= t) <=> (sqrt_rn(max(d2,0)) < R)
    while (__fsqrt_rn(t) >= R) t = __uint_as_float(__float_as_uint(t) - 1u);
    for (;;) {
        float nt = __uint_as_float(__float_as_uint(t) + 1u);
        if (__fsqrt_rn(nt) < R) t = nt; else break;
    }
    g_T = t;
}

// ---------------- detect mask dtype from raw bytes ----------------
__global__ void k_detect(const unsigned char* __restrict__ mraw) {
    int i = blockIdx.x * blockDim.x + threadIdx.x;
    int flags = 0;
    for (; i < NPT; i += gridDim.x * blockDim.x) {
        int r = i & 3;
        if (r != 0 && mraw[i] != 0) flags |= (r == 1) ? 1 : 2;
    }
    if (flags) atomicOr(&g_mtype, flags);
}

__device__ __forceinline__ bool read_mask(const void* mp, int i, int mt) {
    if (mt & 1) return ((const unsigned char*)mp)[i] != 0;   // u8 / bool
    if (mt & 2) return ((const float*)mp)[i] != 0.0f;        // f32 0/1
    return ((const int*)mp)[i] != 0;                          // i32
}

// ---------------- pack points (x,y,z,sq) + per-column density threshold ----------------
__global__ void k_pack(const float* __restrict__ pts, const void* __restrict__ mraw) {
    int i = blockIdx.x * blockDim.x + threadIdx.x;
    if (i >= NPT) return;
    int mt = g_mtype;
    float x = pts[i * 3 + 0], y = pts[i * 3 + 1], z = pts[i * 3 + 2];
    float sq = __fadd_rn(__fadd_rn(__fmul_rn(x, x), __fmul_rn(y, y)), __fmul_rn(z, z));
    g_pts4[i] = make_float4(x, y, z, sq);
    bool mk = read_mask(mraw, i, mt);
    g_Tj[i] = mk ? g_T : __int_as_float(0xff800000); // -inf
}

// ---------------- masked centroid per batch (fp64 accumulate) ----------------
__global__ void k_center() {
    __shared__ double red[256 * 4];
    int b = blockIdx.x, tid = threadIdx.x;
    double sx = 0, sy = 0, sz = 0, c = 0;
    for (int n = tid; n < NN; n += 256) {
        int i = b * NN + n;
        if (g_Tj[i] > 0.0f) {
            float4 p = g_pts4[i];
            sx += (double)p.x; sy += (double)p.y; sz += (double)p.z; c += 1.0;
        }
    }
    red[tid] = sx; red[256 + tid] = sy; red[512 + tid] = sz; red[768 + tid] = c;
    __syncthreads();
    for (int s = 128; s > 0; s >>= 1) {
        if (tid < s) {
            red[tid]       += red[tid + s];
            red[256 + tid] += red[256 + tid + s];
            red[512 + tid] += red[512 + tid + s];
            red[768 + tid] += red[768 + tid + s];
        }
        __syncthreads();
    }
    if (tid == 0) {
        double cm = red[768] > 1.0 ? red[768] : 1.0;
        g_center[b][0] = (float)(red[0]   / cm);
        g_center[b][1] = (float)(red[256] / cm);
        g_center[b][2] = (float)(red[512] / cm);
        g_masksum[b]   = (float)red[768];
    }
}

// ---------------- analytic eigenvalues of symmetric 3x3 (fp64) ----------------
__device__ __forceinline__ float curv_from_cov(float c00, float c01, float c02,
                                               float c11, float c12, float c22) {
    double a00 = c00, a01 = c01, a02 = c02, a11 = c11, a12 = c12, a22 = c22;
    double p1 = a01 * a01 + a02 * a02 + a12 * a12;
    double q  = (a00 + a11 + a22) / 3.0;
    double d0 = a00 - q, d1 = a11 - q, d2v = a22 - q;
    double p2 = d0 * d0 + d1 * d1 + d2v * d2v + 2.0 * p1;
    double emin, emax;
    if (!(p2 > 0.0)) {
        emin = q; emax = q;
    } else {
        double p = sqrt(p2 / 6.0);
        double ip = 1.0 / p;
        double b00 = d0 * ip, b11 = d1 * ip, b22 = d2v * ip;
        double b01 = a01 * ip, b02 = a02 * ip, b12 = a12 * ip;
        double detB = b00 * (b11 * b22 - b12 * b12)
                    - b01 * (b01 * b22 - b12 * b02)
                    + b02 * (b01 * b12 - b11 * b02);
        double r = 0.5 * detB;
        r = fmin(1.0, fmax(-1.0, r));
        double phi = acos(r) / 3.0;
        emax = q + 2.0 * p * cos(phi);
        emin = q + 2.0 * p * cos(phi + 2.0943951023931953); // + 2*pi/3
    }
    float e0 = (float)emin, e2 = (float)emax;
    return e0 / (e2 + 1e-8f);
}

// ---------------- the big O(N^2) scan: exact 10-NN + density ----------------
__global__ void __launch_bounds__(128) k_geom() {
    __shared__ float4 sp[TILE];
    __shared__ float  sT[TILE];
    int b = blockIdx.y;
    int n = blockIdx.x * 128 + threadIdx.x;
    const float4* __restrict__ pts = g_pts4 + b * NN;
    const float*  __restrict__ Tj  = g_Tj  + b * NN;

    float4 pi = pts[n];
    float bestd[KNN];
    int   besti[KNN];
#pragma unroll
    for (int k = 0; k < KNN; k++) { bestd[k] = __int_as_float(0x7f800000); besti[k] = 0; }
    int cnt = 0;

    for (int base = 0; base < NN; base += TILE) {
        __syncthreads();
        for (int t = threadIdx.x; t < TILE; t += 128) {
            sp[t] = pts[base + t];
            sT[t] = Tj[base + t];
        }
        __syncthreads();
#pragma unroll 8
        for (int jj = 0; jj < TILE; ++jj) {
            float4 pj = sp[jj];
            float dot = fmaf(pi.x, pj.x, fmaf(pi.y, pj.y, pi.z * pj.z));
            float d2  = fmaf(-2.0f, dot, pi.w + pj.w);   // sq_i + sq_j - 2*dot
            if (d2 <= sT[jj]) cnt++;                      // exact density test
            if (d2 < bestd[KNN - 1]) {                    // strict <: keeps lower index on ties
                float v = d2; int vi = base + jj;
#pragma unroll
                for (int k = 0; k < KNN; k++) {
                    if (v < bestd[k]) {
                        float tf = bestd[k]; bestd[k] = v; v = tf;
                        int   ti = besti[k]; besti[k] = vi; vi = ti;
                    }
                }
            }
        }
    }

    // covariance of (neighbors - p_i), over the 10 nearest
    float c00 = 0, c01 = 0, c02 = 0, c11 = 0, c12 = 0, c22 = 0;
#pragma unroll
    for (int k = 0; k < KNN; k++) {
        float4 qk = pts[besti[k]];
        float dx = qk.x - pi.x, dy = qk.y - pi.y, dz = qk.z - pi.z;
        c00 = fmaf(dx, dx, c00); c01 = fmaf(dx, dy, c01); c02 = fmaf(dx, dz, c02);
        c11 = fmaf(dy, dy, c11); c12 = fmaf(dy, dz, c12); c22 = fmaf(dz, dz, c22);
    }
    c00 = __fdiv_rn(c00, 10.0f); c01 = __fdiv_rn(c01, 10.0f); c02 = __fdiv_rn(c02, 10.0f);
    c11 = __fdiv_rn(c11, 10.0f); c12 = __fdiv_rn(c12, 10.0f); c22 = __fdiv_rn(c22, 10.0f);
    float curv = curv_from_cov(c00, c01, c02, c11, c12, c22);

    float cx = g_center[b][0], cy = g_center[b][1], cz = g_center[b][2];
    float rx = pi.x - cx, ry = pi.y - cy, rz = pi.z - cz;
    float distc = __fsqrt_rn(__fadd_rn(__fadd_rn(__fmul_rn(rx, rx), __fmul_rn(ry, ry)), __fmul_rn(rz, rz)));
    float horiz = __fsqrt_rn(__fadd_rn(__fmul_rn(rx, rx), __fmul_rn(ry, ry)));
    float rad   = atan2f(ry, rx);
    float dens  = (float)cnt;

    bool valid = g_masksum[b] > 0.0f;
    int i = b * NN + n;
    g_geom[i * 6 + 0] = valid ? distc : 0.0f;
    g_geom[i * 6 + 1] = valid ? rz    : 0.0f;
    g_geom[i * 6 + 2] = valid ? horiz : 0.0f;
    g_geom[i * 6 + 3] = valid ? dens  : 0.0f;
    g_geom[i * 6 + 4] = valid ? curv  : 0.0f;
    g_geom[i * 6 + 5] = valid ? rad   : 0.0f;
}

// ---------------- fused 2-layer MLP: out = relu(relu([feat|geom]@W1+b1)@W2+b2) ----------------
// block: 64 points x 128 cols, 256 threads, weights + activations in shared
__global__ void __launch_bounds__(256) k_mlp(const float* __restrict__ feat,
                                             const float* __restrict__ W1,
                                             const float* __restrict__ b1,
                                             const float* __restrict__ W2,
                                             const float* __restrict__ b2,
                                             float* __restrict__ out) {
    extern __shared__ float sm[];
    float* sW1 = sm;            // 70*128   = 8960
    float* sB1 = sm + 8960;     // 128
    float* sW2 = sm + 9088;     // 128*128  = 16384
    float* sB2 = sm + 25472;    // 128
    float* sX  = sm + 25600;    // 64*72    = 4608
    float* sH  = sm + 30208;    // 64*132   = 8448   (total 38656 floats = 154624 B)

    int tid = threadIdx.x;
    for (int i = tid; i < 8960;  i += 256) sW1[i] = W1[i];
    for (int i = tid; i < 16384; i += 256) sW2[i] = W2[i];
    if (tid < 128) { sB1[tid] = b1[tid]; sB2[tid] = b2[tid]; }

    int m0 = blockIdx.x * 64;
    for (int i = tid; i < 64 * 70; i += 256) {
        int r = i / 70, c = i % 70;
        int m = m0 + r;
        sX[r * 72 + c] = (c < 64) ? feat[m * 64 + c] : g_geom[m * 6 + (c - 64)];
    }
    __syncthreads();

    int cg = tid & 31;   // col group: cols cg*4 .. cg*4+3
    int rg = tid >> 5;   // row group: rows rg*8 .. rg*8+7

    float acc[8][4];
#pragma unroll
    for (int r = 0; r < 8; r++)
#pragma unroll
        for (int c = 0; c < 4; c++) acc[r][c] = 0.0f;

    for (int k = 0; k < 70; k++) {
        float4 w = *(const float4*)(sW1 + k * 128 + cg * 4);
#pragma unroll
        for (int r = 0; r < 8; r++) {
            float xv = sX[(rg * 8 + r) * 72 + k];
            acc[r][0] = fmaf(xv, w.x, acc[r][0]);
            acc[r][1] = fmaf(xv, w.y, acc[r][1]);
            acc[r][2] = fmaf(xv, w.z, acc[r][2]);
            acc[r][3] = fmaf(xv, w.w, acc[r][3]);
        }
    }
    {
        float4 bv = *(const float4*)(sB1 + cg * 4);
#pragma unroll
        for (int r = 0; r < 8; r++) {
            float4 h;
            h.x = fmaxf(acc[r][0] + bv.x, 0.0f);
            h.y = fmaxf(acc[r][1] + bv.y, 0.0f);
            h.z = fmaxf(acc[r][2] + bv.z, 0.0f);
            h.w = fmaxf(acc[r][3] + bv.w, 0.0f);
            *(float4*)(sH + (rg * 8 + r) * 132 + cg * 4) = h;
        }
    }
    __syncthreads();

#pragma unroll
    for (int r = 0; r < 8; r++)
#pragma unroll
        for (int c = 0; c < 4; c++) acc[r][c] = 0.0f;

    for (int k = 0; k < 128; k++) {
        float4 w = *(const float4*)(sW2 + k * 128 + cg * 4);
#pragma unroll
        for (int r = 0; r < 8; r++) {
            float hv = sH[(rg * 8 + r) * 132 + k];
            acc[r][0] = fmaf(hv, w.x, acc[r][0]);
            acc[r][1] = fmaf(hv, w.y, acc[r][1]);
            acc[r][2] = fmaf(hv, w.z, acc[r][2]);
            acc[r][3] = fmaf(hv, w.w, acc[r][3]);
        }
    }
    {
        float4 bv = *(const float4*)(sB2 + cg * 4);
#pragma unroll
        for (int r = 0; r < 8; r++) {
            float4 o;
            o.x = fmaxf(acc[r][0] + bv.x, 0.0f);
            o.y = fmaxf(acc[r][1] + bv.y, 0.0f);
            o.z = fmaxf(acc[r][2] + bv.z, 0.0f);
            o.w = fmaxf(acc[r][3] + bv.w, 0.0f);
            *(float4*)(out + (size_t)(m0 + rg * 8 + r) * 128 + cg * 4) = o;
        }
    }
}

// ---------------- launch ----------------
extern "C" void kernel_launch(void* const* d_in, const int* in_sizes, int n_in,
                              void* d_out, int out_size) {
    const float* points = (const float*)d_in[0];
    const float* feat   = (const float*)d_in[1];
    const void*  mask   = d_in[2];
    const float* W1     = (const float*)d_in[3];
    const float* b1     = (const float*)d_in[4];
    const float* W2     = (const float*)d_in[5];
    const float* b2     = (const float*)d_in[6];
    float* out = (float*)d_out;

    cudaFuncSetAttribute(k_mlp, cudaFuncAttributeMaxDynamicSharedMemorySize, 160 * 1024);

    k_init<<<1, 1>>>();
    k_detect<<<16, 256>>>((const unsigned char*)mask);
    k_pack<<<(NPT + 255) / 256, 256>>>(points, mask);
    k_center<<<BB, 256>>>();
    k_geom<<<dim3(NN / 128, BB), 128>>>();
    k_mlp<<<NPT / 64, 256, 154624>>>(feat, W1, b1, W2, b2, out);
}

// round 2
// speedup vs baseline: 2.6177x; 2.6177x over previous
#include <cuda_runtime.h>
#include <math.h>

#define BB 2
#define NN 8192
#define NPT (BB*NN)
#define KNN 10
#define GRID 16
#define GC (GRID*GRID*GRID)
#define HCELL 0.0625f

// ---------------- device scratch (no allocations allowed) ----------------
__device__ float4 g_sp4[NPT];          // sorted points (x,y,z,sq)
__device__ float  g_sT[NPT];           // sorted: mask? T : -inf
__device__ int    g_sidx[NPT];         // sorted -> original global index
__device__ int    g_cnt[BB*GC];        // per-cell counts
__device__ int    g_start[BB*GC];      // per-cell exclusive prefix (within batch)
__device__ int    g_cur[BB*GC];        // scatter cursors
__device__ double g_cacc[BB][4];       // masked centroid sums + count
__device__ float  g_geom[NPT * 6];
__device__ int    g_mtype;
__device__ float  g_T;                 // exact density d2 threshold

// ---------------- f32x2 helpers ----------------
#define FMA2(d, a, b) asm("fma.rn.f32x2 %0, %1, %2, %3;" : "=l"(d) : "l"(a), "l"(b), "l"(d))
__device__ __forceinline__ unsigned long long pack2(float v) {
    unsigned long long r; unsigned u = __float_as_uint(v);
    asm("mov.b64 %0, {%1, %1};" : "=l"(r) : "r"(u));
    return r;
}
__device__ __forceinline__ void unpack2(unsigned long long v, float& lo, float& hi) {
    unsigned a, b;
    asm("mov.b64 {%0, %1}, %2;" : "=r"(a), "=r"(b) : "l"(v));
    lo = __uint_as_float(a); hi = __uint_as_float(b);
}

// ---------------- init: zero state + exact sqrt threshold ----------------
__global__ void k_init() {
    int i = blockIdx.x * blockDim.x + threadIdx.x;
    if (i < BB * GC) g_cnt[i] = 0;
    if (i == 0) {
        g_mtype = 0;
        for (int b = 0; b < BB; b++)
            for (int c = 0; c < 4; c++) g_cacc[b][c] = 0.0;
        const float R = 0.02f;
        float t = __fmul_rn(R, R);
        while (__fsqrt_rn(t) >= R) t = __uint_as_float(__float_as_uint(t) - 1u);
        for (;;) {
            float nt = __uint_as_float(__float_as_uint(t) + 1u);
            if (__fsqrt_rn(nt) < R) t = nt; else break;
        }
        g_T = t;
    }
}

__device__ __forceinline__ int cell_of(float x, float y, float z) {
    int cx = min(GRID - 1, max(0, (int)(x * (float)GRID)));
    int cy = min(GRID - 1, max(0, (int)(y * (float)GRID)));
    int cz = min(GRID - 1, max(0, (int)(z * (float)GRID)));
    return (cz * GRID + cy) * GRID + cx;
}

// ---------------- count pass + mask dtype detection ----------------
__global__ void k_count(const float* __restrict__ pts, const unsigned char* __restrict__ mraw) {
    int i = blockIdx.x * blockDim.x + threadIdx.x;
    if (i >= NPT) return;
    float x = pts[i * 3 + 0], y = pts[i * 3 + 1], z = pts[i * 3 + 2];
    int b = i / NN;
    atomicAdd(&g_cnt[b * GC + cell_of(x, y, z)], 1);
    // mask dtype detection from raw bytes (first NPT bytes are enough)
    unsigned char mb = mraw[i];
    int r = i & 3;
    bool f1 = (r == 1) && mb;
    bool f2 = (r >= 2) && mb;
    unsigned m1 = __ballot_sync(0xFFFFFFFFu, f1);
    unsigned m2 = __ballot_sync(0xFFFFFFFFu, f2);
    if ((threadIdx.x & 31) == 0 && (m1 | m2))
        atomicOr(&g_mtype, (m1 ? 1 : 0) | (m2 ? 2 : 0));
}

__device__ __forceinline__ bool read_mask(const void* mp, int i, int mt) {
    if (mt & 1) return ((const unsigned char*)mp)[i] != 0;
    if (mt & 2) return ((const float*)mp)[i] != 0.0f;
    return ((const int*)mp)[i] != 0;
}

// ---------------- per-batch exclusive scan over 4096 cells ----------------
__global__ void k_scan() {
    __shared__ int part[256];
    int b = blockIdx.x, t = threadIdx.x;
    int base = b * GC + t * 16;
    int loc[16]; int s = 0;
#pragma unroll
    for (int k = 0; k < 16; k++) { loc[k] = s; s += g_cnt[base + k]; }
    part[t] = s;
    __syncthreads();
    for (int d = 1; d < 256; d <<= 1) {
        int v = (t >= d) ? part[t - d] : 0;
        __syncthreads();
        part[t] += v;
        __syncthreads();
    }
    int off = part[t] - s;
#pragma unroll
    for (int k = 0; k < 16; k++) {
        g_start[base + k] = off + loc[k];
        g_cur[base + k]   = off + loc[k];
    }
}

// ---------------- scatter into sorted order + masked centroid ----------------
__global__ void k_scatter(const float* __restrict__ pts, const void* __restrict__ mraw) {
    int i = blockIdx.x * blockDim.x + threadIdx.x;
    if (i >= NPT) return;
    int mt = g_mtype;
    float x = pts[i * 3 + 0], y = pts[i * 3 + 1], z = pts[i * 3 + 2];
    float sq = __fadd_rn(__fadd_rn(__fmul_rn(x, x), __fmul_rn(y, y)), __fmul_rn(z, z));
    int b = i / NN;
    int cell = b * GC + cell_of(x, y, z);
    bool mk = read_mask(mraw, i, mt);
    int pos = atomicAdd(&g_cur[cell], 1);       // within-batch slot
    int dst = b * NN + pos;
    g_sp4[dst]  = make_float4(x, y, z, sq);
    g_sT[dst]   = mk ? g_T : __int_as_float(0xff800000);
    g_sidx[dst] = i;
    // warp-reduced masked centroid (warps never straddle batches: NN % 32 == 0)
    double vx = mk ? (double)x : 0.0, vy = mk ? (double)y : 0.0;
    double vz = mk ? (double)z : 0.0, vc = mk ? 1.0 : 0.0;
#pragma unroll
    for (int o = 16; o > 0; o >>= 1) {
        vx += __shfl_down_sync(0xFFFFFFFFu, vx, o);
        vy += __shfl_down_sync(0xFFFFFFFFu, vy, o);
        vz += __shfl_down_sync(0xFFFFFFFFu, vz, o);
        vc += __shfl_down_sync(0xFFFFFFFFu, vc, o);
    }
    if ((threadIdx.x & 31) == 0) {
        atomicAdd(&g_cacc[b][0], vx);
        atomicAdd(&g_cacc[b][1], vy);
        atomicAdd(&g_cacc[b][2], vz);
        atomicAdd(&g_cacc[b][3], vc);
    }
}

// ---------------- analytic eigenvalues of symmetric 3x3 (fp64) ----------------
__device__ __forceinline__ float curv_from_cov(float c00, float c01, float c02,
                                               float c11, float c12, float c22) {
    double a00 = c00, a01 = c01, a02 = c02, a11 = c11, a12 = c12, a22 = c22;
    double p1 = a01 * a01 + a02 * a02 + a12 * a12;
    double q  = (a00 + a11 + a22) / 3.0;
    double d0 = a00 - q, d1 = a11 - q, d2v = a22 - q;
    double p2 = d0 * d0 + d1 * d1 + d2v * d2v + 2.0 * p1;
    double emin, emax;
    if (!(p2 > 0.0)) { emin = q; emax = q; }
    else {
        double p = sqrt(p2 / 6.0);
        double ip = 1.0 / p;
        double b00 = d0 * ip, b11 = d1 * ip, b22 = d2v * ip;
        double b01 = a01 * ip, b02 = a02 * ip, b12 = a12 * ip;
        double detB = b00 * (b11 * b22 - b12 * b12)
                    - b01 * (b01 * b22 - b12 * b02)
                    + b02 * (b01 * b12 - b11 * b02);
        double r = 0.5 * detB;
        r = fmin(1.0, fmax(-1.0, r));
        double phi = acos(r) / 3.0;
        emax = q + 2.0 * p * cos(phi);
        emin = q + 2.0 * p * cos(phi + 2.0943951023931953);
    }
    float e0 = (float)emin, e2 = (float)emax;
    return e0 / (e2 + 1e-8f);
}

// ---------------- candidate-cell scan ----------------
__device__ __forceinline__ void scan_cell(int cidx, int boff, float4 pi,
                                          unsigned long long (&best)[KNN], int& cnt) {
    int st = g_start[cidx];
    int en = st + g_cnt[cidx];
    for (int j = st; j < en; ++j) {
        float4 pj = g_sp4[boff + j];
        float Tv  = g_sT[boff + j];
        float dot = fmaf(pi.x, pj.x, fmaf(pi.y, pj.y, pi.z * pj.z));
        float d2  = fmaf(-2.0f, dot, pi.w + pj.w);
        if (d2 <= Tv) cnt++;
        float d2c = fmaxf(d2, 0.0f);
        unsigned long long key =
            ((unsigned long long)__float_as_uint(d2c) << 32) | (unsigned)j;
        if (key < best[KNN - 1]) {
#pragma unroll
            for (int k = 0; k < KNN; k++) {
                if (key < best[k]) {
                    unsigned long long tmp = best[k]; best[k] = key; key = tmp;
                }
            }
        }
    }
}

// ---------------- grid-accelerated exact 10-NN + density ----------------
__global__ void __launch_bounds__(128) k_geom() {
    int t = blockIdx.x * 128 + threadIdx.x;
    int b = t / NN, s = t % NN;
    int boff  = b * NN;
    int cbase = b * GC;
    float4 pi = g_sp4[boff + s];
    int orig  = g_sidx[boff + s];

    int cix = min(GRID - 1, max(0, (int)(pi.x * (float)GRID)));
    int ciy = min(GRID - 1, max(0, (int)(pi.y * (float)GRID)));
    int ciz = min(GRID - 1, max(0, (int)(pi.z * (float)GRID)));

    unsigned long long best[KNN];
#pragma unroll
    for (int k = 0; k < KNN; k++) best[k] = 0xFFFFFFFFFFFFFFFFull;
    int cnt = 0;

    // rings 0..1 (always searched; provably contains all density candidates)
    for (int zz = max(ciz - 1, 0); zz <= min(ciz + 1, GRID - 1); zz++)
        for (int yy = max(ciy - 1, 0); yy <= min(ciy + 1, GRID - 1); yy++)
            for (int xx = max(cix - 1, 0); xx <= min(cix + 1, GRID - 1); xx++)
                scan_cell(cbase + (zz * GRID + yy) * GRID + xx, boff, pi, best, cnt);

    // expand shells until 10th-best squared dist < (r*h)^2  (exactness bound)
    for (int r = 1;; ) {
        float d10 = __uint_as_float((unsigned)(best[KNN - 1] >> 32));
        float bnd = (float)r * HCELL;
        if (d10 < bnd * bnd || r >= GRID - 1) break;
        r++;
        for (int zz = ciz - r; zz <= ciz + r; zz++) {
            if (zz < 0 || zz >= GRID) continue;
            int az = abs(zz - ciz);
            for (int yy = ciy - r; yy <= ciy + r; yy++) {
                if (yy < 0 || yy >= GRID) continue;
                int ay = abs(yy - ciy);
                for (int xx = cix - r; xx <= cix + r; xx++) {
                    if (xx < 0 || xx >= GRID) continue;
                    int ax = abs(xx - cix);
                    int ch = max(ax, max(ay, az));
                    if (ch != r) continue;
                    scan_cell(cbase + (zz * GRID + yy) * GRID + xx, boff, pi, best, cnt);
                }
            }
        }
    }

    // covariance of (neighbors - p_i)
    float c00 = 0, c01 = 0, c02 = 0, c11 = 0, c12 = 0, c22 = 0;
#pragma unroll
    for (int k = 0; k < KNN; k++) {
        int j = (int)(unsigned)(best[k] & 0xFFFFFFFFull);
        float4 qk = g_sp4[boff + j];
        float dx = qk.x - pi.x, dy = qk.y - pi.y, dz = qk.z - pi.z;
        c00 = fmaf(dx, dx, c00); c01 = fmaf(dx, dy, c01); c02 = fmaf(dx, dz, c02);
        c11 = fmaf(dy, dy, c11); c12 = fmaf(dy, dz, c12); c22 = fmaf(dz, dz, c22);
    }
    c00 = __fdiv_rn(c00, 10.0f); c01 = __fdiv_rn(c01, 10.0f); c02 = __fdiv_rn(c02, 10.0f);
    c11 = __fdiv_rn(c11, 10.0f); c12 = __fdiv_rn(c12, 10.0f); c22 = __fdiv_rn(c22, 10.0f);
    float curv = curv_from_cov(c00, c01, c02, c11, c12, c22);

    double cm   = g_cacc[b][3];
    double cden = cm > 1.0 ? cm : 1.0;
    float cx = (float)(g_cacc[b][0] / cden);
    float cy = (float)(g_cacc[b][1] / cden);
    float cz = (float)(g_cacc[b][2] / cden);
    float rx = pi.x - cx, ry = pi.y - cy, rz = pi.z - cz;
    float distc = __fsqrt_rn(__fadd_rn(__fadd_rn(__fmul_rn(rx, rx), __fmul_rn(ry, ry)), __fmul_rn(rz, rz)));
    float horiz = __fsqrt_rn(__fadd_rn(__fmul_rn(rx, rx), __fmul_rn(ry, ry)));
    float rad   = atan2f(ry, rx);
    float dens  = (float)cnt;

    bool valid = cm > 0.0;
    g_geom[orig * 6 + 0] = valid ? distc : 0.0f;
    g_geom[orig * 6 + 1] = valid ? rz    : 0.0f;
    g_geom[orig * 6 + 2] = valid ? horiz : 0.0f;
    g_geom[orig * 6 + 3] = valid ? dens  : 0.0f;
    g_geom[orig * 6 + 4] = valid ? curv  : 0.0f;
    g_geom[orig * 6 + 5] = valid ? rad   : 0.0f;
}

// ---------------- fused 2-layer MLP with f32x2 FMA, 128 rows/block, 1 wave ----------------
__global__ void __launch_bounds__(256) k_mlp(const float* __restrict__ feat,
                                             const float* __restrict__ W1,
                                             const float* __restrict__ b1,
                                             const float* __restrict__ W2,
                                             const float* __restrict__ b2,
                                             float* __restrict__ out) {
    extern __shared__ float sm[];
    float* sW1 = sm;             // 70*128   = 8960
    float* sB1 = sm + 8960;      // 128
    float* sW2 = sm + 9088;      // 128*128  = 16384
    float* sB2 = sm + 25472;     // 128
    float* sX  = sm + 25600;     // 128*72   = 9216
    float* sH  = sm + 34816;     // 128*132  = 16896  (total 51712 floats = 206848 B)

    int tid = threadIdx.x;
    for (int i = tid; i < 8960;  i += 256) sW1[i] = W1[i];
    for (int i = tid; i < 16384; i += 256) sW2[i] = W2[i];
    if (tid < 128) { sB1[tid] = b1[tid]; sB2[tid] = b2[tid]; }

    int m0 = blockIdx.x * 128;
    for (int i = tid; i < 128 * 64; i += 256) {        // coalesced feature load
        int r = i >> 6, c = i & 63;
        sX[r * 72 + c] = feat[(m0 + r) * 64 + c];
    }
    for (int i = tid; i < 128 * 6; i += 256) {
        int r = i / 6, c = i % 6;
        sX[r * 72 + 64 + c] = g_geom[(m0 + r) * 6 + c];
    }
    __syncthreads();

    int cg = tid & 31;   // cols cg*4 .. cg*4+3
    int rg = tid >> 5;   // rows rg*16 .. rg*16+15

    unsigned long long acc[16][2];
#pragma unroll
    for (int r = 0; r < 16; r++) { acc[r][0] = 0ull; acc[r][1] = 0ull; }

    for (int k = 0; k < 70; k++) {
        ulonglong2 w2 = *(const ulonglong2*)(sW1 + k * 128 + cg * 4);
#pragma unroll
        for (int r = 0; r < 16; r++) {
            unsigned long long xp = pack2(sX[(rg * 16 + r) * 72 + k]);
            FMA2(acc[r][0], w2.x, xp);
            FMA2(acc[r][1], w2.y, xp);
        }
    }
    {
        float4 bv = *(const float4*)(sB1 + cg * 4);
#pragma unroll
        for (int r = 0; r < 16; r++) {
            float a0, a1, a2, a3;
            unpack2(acc[r][0], a0, a1);
            unpack2(acc[r][1], a2, a3);
            float4 h;
            h.x = fmaxf(a0 + bv.x, 0.0f);
            h.y = fmaxf(a1 + bv.y, 0.0f);
            h.z = fmaxf(a2 + bv.z, 0.0f);
            h.w = fmaxf(a3 + bv.w, 0.0f);
            *(float4*)(sH + (rg * 16 + r) * 132 + cg * 4) = h;
        }
    }
    __syncthreads();

#pragma unroll
    for (int r = 0; r < 16; r++) { acc[r][0] = 0ull; acc[r][1] = 0ull; }

    for (int k = 0; k < 128; k++) {
        ulonglong2 w2 = *(const ulonglong2*)(sW2 + k * 128 + cg * 4);
#pragma unroll
        for (int r = 0; r < 16; r++) {
            unsigned long long hp = pack2(sH[(rg * 16 + r) * 132 + k]);
            FMA2(acc[r][0], w2.x, hp);
            FMA2(acc[r][1], w2.y, hp);
        }
    }
    {
        float4 bv = *(const float4*)(sB2 + cg * 4);
#pragma unroll
        for (int r = 0; r < 16; r++) {
            float a0, a1, a2, a3;
            unpack2(acc[r][0], a0, a1);
            unpack2(acc[r][1], a2, a3);
            float4 o;
            o.x = fmaxf(a0 + bv.x, 0.0f);
            o.y = fmaxf(a1 + bv.y, 0.0f);
            o.z = fmaxf(a2 + bv.z, 0.0f);
            o.w = fmaxf(a3 + bv.w, 0.0f);
            *(float4*)(out + (size_t)(m0 + rg * 16 + r) * 128 + cg * 4) = o;
        }
    }
}

// ---------------- launch ----------------
extern "C" void kernel_launch(void* const* d_in, const int* in_sizes, int n_in,
                              void* d_out, int out_size) {
    const float* points = (const float*)d_in[0];
    const float* feat   = (const float*)d_in[1];
    const void*  mask   = d_in[2];
    const float* W1     = (const float*)d_in[3];
    const float* b1     = (const float*)d_in[4];
    const float* W2     = (const float*)d_in[5];
    const float* b2     = (const float*)d_in[6];
    float* out = (float*)d_out;

    cudaFuncSetAttribute(k_mlp, cudaFuncAttributeMaxDynamicSharedMemorySize, 212992);

    k_init   <<<(BB * GC + 255) / 256, 256>>>();
    k_count  <<<(NPT + 255) / 256, 256>>>(points, (const unsigned char*)mask);
    k_scan   <<<BB, 256>>>();
    k_scatter<<<(NPT + 255) / 256, 256>>>(points, mask);
    k_geom   <<<NPT / 128, 128>>>();
    k_mlp    <<<NPT / 128, 256, 206848>>>(feat, W1, b1, W2, b2, out);
}

// round 3
// speedup vs baseline: 3.1942x; 1.2202x over previous
#include <cuda_runtime.h>
#include <math.h>

#define BB 2
#define NN 8192
#define NPT (BB*NN)
#define KNN 10
#define GRID 16
#define GC (GRID*GRID*GRID)
#define HCELL 0.0625f

// ---------------- device scratch ----------------
__device__ float4 g_sp4[NPT];        // sorted points (x,y,z, sq with sign bit = mask)
__device__ int    g_sidx[NPT];       // sorted -> original index
__device__ int    g_cnt[BB*GC];
__device__ int2   g_range[BB*GC];    // (start,end) within batch
__device__ int    g_cur[BB*GC];
__device__ double g_cacc[BB][4];     // masked centroid sums + count
__device__ float  g_geom[NPT * 6];
__device__ int    g_mtype;
__device__ float  g_T;

// ---------------- f32x2 helpers ----------------
#define FMA2(d, a, b) asm("fma.rn.f32x2 %0, %1, %2, %3;" : "=l"(d) : "l"(a), "l"(b), "l"(d))
__device__ __forceinline__ unsigned long long pack2(float v) {
    unsigned long long r; unsigned u = __float_as_uint(v);
    asm("mov.b64 %0, {%1, %1};" : "=l"(r) : "r"(u));
    return r;
}
__device__ __forceinline__ void unpack2(unsigned long long v, float& lo, float& hi) {
    unsigned a, b;
    asm("mov.b64 {%0, %1}, %2;" : "=r"(a), "=r"(b) : "l"(v));
    lo = __uint_as_float(a); hi = __uint_as_float(b);
}

// ---------------- init ----------------
__global__ void k_init() {
    int i = blockIdx.x * blockDim.x + threadIdx.x;
    if (i < BB * GC) g_cnt[i] = 0;
    if (i == 0) {
        g_mtype = 0;
        for (int b = 0; b < BB; b++)
            for (int c = 0; c < 4; c++) g_cacc[b][c] = 0.0;
        const float R = 0.02f;
        float t = __fmul_rn(R, R);
        while (__fsqrt_rn(t) >= R) t = __uint_as_float(__float_as_uint(t) - 1u);
        for (;;) {
            float nt = __uint_as_float(__float_as_uint(t) + 1u);
            if (__fsqrt_rn(nt) < R) t = nt; else break;
        }
        g_T = t;
    }
}

__device__ __forceinline__ int cell_of(float x, float y, float z) {
    int cx = min(GRID - 1, max(0, (int)(x * (float)GRID)));
    int cy = min(GRID - 1, max(0, (int)(y * (float)GRID)));
    int cz = min(GRID - 1, max(0, (int)(z * (float)GRID)));
    return (cz * GRID + cy) * GRID + cx;
}

// ---------------- count + mask dtype detect ----------------
__global__ void k_count(const float* __restrict__ pts, const unsigned char* __restrict__ mraw) {
    int i = blockIdx.x * blockDim.x + threadIdx.x;
    if (i >= NPT) return;
    float x = pts[i * 3 + 0], y = pts[i * 3 + 1], z = pts[i * 3 + 2];
    int b = i / NN;
    atomicAdd(&g_cnt[b * GC + cell_of(x, y, z)], 1);
    unsigned char mb = mraw[i];
    int r = i & 3;
    unsigned m1 = __ballot_sync(0xFFFFFFFFu, (r == 1) && mb);
    unsigned m2 = __ballot_sync(0xFFFFFFFFu, (r >= 2) && mb);
    if ((threadIdx.x & 31) == 0 && (m1 | m2))
        atomicOr(&g_mtype, (m1 ? 1 : 0) | (m2 ? 2 : 0));
}

__device__ __forceinline__ bool read_mask(const void* mp, int i, int mt) {
    if (mt & 1) return ((const unsigned char*)mp)[i] != 0;
    if (mt & 2) return ((const float*)mp)[i] != 0.0f;
    return ((const int*)mp)[i] != 0;
}

// ---------------- per-batch exclusive scan over 4096 cells ----------------
__global__ void k_scan() {
    __shared__ int part[256];
    int b = blockIdx.x, t = threadIdx.x;
    int base = b * GC + t * 16;
    int loc[16]; int s = 0;
#pragma unroll
    for (int k = 0; k < 16; k++) { loc[k] = s; s += g_cnt[base + k]; }
    part[t] = s;
    __syncthreads();
    for (int d = 1; d < 256; d <<= 1) {
        int v = (t >= d) ? part[t - d] : 0;
        __syncthreads();
        part[t] += v;
        __syncthreads();
    }
    int off = part[t] - s;
#pragma unroll
    for (int k = 0; k < 16; k++) {
        int st = off + loc[k];
        g_range[base + k] = make_int2(st, st + g_cnt[base + k]);
        g_cur[base + k]   = st;
    }
}

// ---------------- scatter + masked centroid ----------------
__global__ void k_scatter(const float* __restrict__ pts, const void* __restrict__ mraw) {
    int i = blockIdx.x * blockDim.x + threadIdx.x;
    if (i >= NPT) return;
    int mt = g_mtype;
    float x = pts[i * 3 + 0], y = pts[i * 3 + 1], z = pts[i * 3 + 2];
    float sq = __fadd_rn(__fadd_rn(__fmul_rn(x, x), __fmul_rn(y, y)), __fmul_rn(z, z));
    int b = i / NN;
    int cell = b * GC + cell_of(x, y, z);
    bool mk = read_mask(mraw, i, mt);
    float wv = mk ? __uint_as_float(__float_as_uint(sq) | 0x80000000u) : sq;
    int pos = atomicAdd(&g_cur[cell], 1);
    int dst = b * NN + pos;
    g_sp4[dst]  = make_float4(x, y, z, wv);
    g_sidx[dst] = i;
    double vx = mk ? (double)x : 0.0, vy = mk ? (double)y : 0.0;
    double vz = mk ? (double)z : 0.0, vc = mk ? 1.0 : 0.0;
#pragma unroll
    for (int o = 16; o > 0; o >>= 1) {
        vx += __shfl_down_sync(0xFFFFFFFFu, vx, o);
        vy += __shfl_down_sync(0xFFFFFFFFu, vy, o);
        vz += __shfl_down_sync(0xFFFFFFFFu, vz, o);
        vc += __shfl_down_sync(0xFFFFFFFFu, vc, o);
    }
    if ((threadIdx.x & 31) == 0) {
        atomicAdd(&g_cacc[b][0], vx);
        atomicAdd(&g_cacc[b][1], vy);
        atomicAdd(&g_cacc[b][2], vz);
        atomicAdd(&g_cacc[b][3], vc);
    }
}

// ---------------- analytic eigenvalues of symmetric 3x3 (fp64) ----------------
__device__ __forceinline__ float curv_from_cov(float c00, float c01, float c02,
                                               float c11, float c12, float c22) {
    double a00 = c00, a01 = c01, a02 = c02, a11 = c11, a12 = c12, a22 = c22;
    double p1 = a01 * a01 + a02 * a02 + a12 * a12;
    double q  = (a00 + a11 + a22) / 3.0;
    double d0 = a00 - q, d1 = a11 - q, d2v = a22 - q;
    double p2 = d0 * d0 + d1 * d1 + d2v * d2v + 2.0 * p1;
    double emin, emax;
    if (!(p2 > 0.0)) { emin = q; emax = q; }
    else {
        double p = sqrt(p2 / 6.0);
        double ip = 1.0 / p;
        double b00 = d0 * ip, b11 = d1 * ip, b22 = d2v * ip;
        double b01 = a01 * ip, b02 = a02 * ip, b12 = a12 * ip;
        double detB = b00 * (b11 * b22 - b12 * b12)
                    - b01 * (b01 * b22 - b12 * b02)
                    + b02 * (b01 * b12 - b11 * b02);
        double r = 0.5 * detB;
        r = fmin(1.0, fmax(-1.0, r));
        double phi = acos(r) / 3.0;
        emax = q + 2.0 * p * cos(phi);
        emin = q + 2.0 * p * cos(phi + 2.0943951023931953);
    }
    float e0 = (float)emin, e2 = (float)emax;
    return e0 / (e2 + 1e-8f);
}

// ---------------- candidate cell scan (per lane) ----------------
__device__ __forceinline__ void scan_range(int2 rg, int boff, float pix, float piy,
                                           float piz, float piw, float Tloc,
                                           unsigned long long (&best)[KNN], int& cnt) {
    for (int j = rg.x; j < rg.y; ++j) {
        float4 pj = g_sp4[boff + j];
        float sqj = fabsf(pj.w);
        float Tv  = (__float_as_uint(pj.w) & 0x80000000u) ? Tloc : __int_as_float(0xff800000);
        float dot = fmaf(pix, pj.x, fmaf(piy, pj.y, piz * pj.z));
        float d2  = fmaf(-2.0f, dot, piw + sqj);
        if (d2 <= Tv) cnt++;
        float d2c = fmaxf(d2, 0.0f);
        unsigned long long key =
            ((unsigned long long)__float_as_uint(d2c) << 32) | (unsigned)j;
        if (key < best[KNN - 1]) {
#pragma unroll
            for (int k = 0; k < KNN; k++) {
                if (key < best[k]) {
                    unsigned long long tmp = best[k]; best[k] = key; key = tmp;
                }
            }
        }
    }
}

// ---------------- 8-lane cooperative exact 10-NN + density ----------------
__global__ void __launch_bounds__(256) k_geom() {
    int gt = blockIdx.x * 256 + threadIdx.x;
    int p  = gt >> 3;            // point id (sorted)
    int l8 = gt & 7;             // lane within 8-lane group
    int b  = p >> 13;            // NN = 8192
    int s  = p & (NN - 1);
    int boff  = b * NN;
    int cbase = b * GC;

    float4 pi = g_sp4[boff + s];
    float pix = pi.x, piy = pi.y, piz = pi.z, piw = fabsf(pi.w);
    int orig  = g_sidx[boff + s];
    float Tloc = g_T;

    int cix = min(GRID - 1, max(0, (int)(pix * (float)GRID)));
    int ciy = min(GRID - 1, max(0, (int)(piy * (float)GRID)));
    int ciz = min(GRID - 1, max(0, (int)(piz * (float)GRID)));

    unsigned long long best[KNN];
    int cnt;
    float c00, c01, c02, c11, c12, c22;
    unsigned long long d10key;

    for (int R = 2;; R++) {
#pragma unroll
        for (int k = 0; k < KNN; k++) best[k] = 0xFFFFFFFFFFFFFFFFull;
        cnt = 0;
        c00 = c01 = c02 = c11 = c12 = c22 = 0.0f;

        if (R == 2) {
            // specialized 5x5x5 box, lanes stride the 125 linear cells
#pragma unroll 4
            for (int idx = l8; idx < 125; idx += 8) {
                int dz = idx / 25, rem = idx - dz * 25;
                int dy = rem / 5,  dx  = rem - dy * 5;
                int zz = ciz + dz - 2, yy = ciy + dy - 2, xx = cix + dx - 2;
                if ((unsigned)zz < GRID && (unsigned)yy < GRID && (unsigned)xx < GRID) {
                    int2 rg = g_range[cbase + (zz * GRID + yy) * GRID + xx];
                    scan_range(rg, boff, pix, piy, piz, piw, Tloc, best, cnt);
                }
            }
        } else {
            // generic box (rare): counter-distributed cells
            int c = 0;
            for (int zz = ciz - R; zz <= ciz + R; zz++)
                for (int yy = ciy - R; yy <= ciy + R; yy++)
                    for (int xx = cix - R; xx <= cix + R; xx++) {
                        if ((c++ & 7) == l8 &&
                            (unsigned)zz < GRID && (unsigned)yy < GRID && (unsigned)xx < GRID) {
                            int2 rg = g_range[cbase + (zz * GRID + yy) * GRID + xx];
                            scan_range(rg, boff, pix, piy, piz, piw, Tloc, best, cnt);
                        }
                    }
        }

        // merge top-10 across the 8 lanes; owner pops and accumulates covariance
        d10key = 0xFFFFFFFFFFFFFFFFull;
#pragma unroll
        for (int round = 0; round < KNN; round++) {
            unsigned long long m = best[0];
            m = min(m, __shfl_xor_sync(0xFFFFFFFFu, m, 1));
            m = min(m, __shfl_xor_sync(0xFFFFFFFFu, m, 2));
            m = min(m, __shfl_xor_sync(0xFFFFFFFFu, m, 4));
            if (m == best[0] && m != 0xFFFFFFFFFFFFFFFFull) {
                int j = (int)(unsigned)(m & 0xFFFFFFFFull);
                float4 q = g_sp4[boff + j];
                float dx = q.x - pix, dy = q.y - piy, dz = q.z - piz;
                c00 = fmaf(dx, dx, c00); c01 = fmaf(dx, dy, c01); c02 = fmaf(dx, dz, c02);
                c11 = fmaf(dy, dy, c11); c12 = fmaf(dy, dz, c12); c22 = fmaf(dz, dz, c22);
#pragma unroll
                for (int k = 0; k < KNN - 1; k++) best[k] = best[k + 1];
                best[KNN - 1] = 0xFFFFFFFFFFFFFFFFull;
            }
            d10key = m;
        }

        // exactness bound: distance to scanned-box walls (domain edges unconstrained)
        float g = __int_as_float(0x7f800000);
        if (cix - R > 0)        g = fminf(g, pix - (float)(cix - R) * HCELL);
        if (cix + R < GRID - 1) g = fminf(g, (float)(cix + R + 1) * HCELL - pix);
        if (ciy - R > 0)        g = fminf(g, piy - (float)(ciy - R) * HCELL);
        if (ciy + R < GRID - 1) g = fminf(g, (float)(ciy + R + 1) * HCELL - piy);
        if (ciz - R > 0)        g = fminf(g, piz - (float)(ciz - R) * HCELL);
        if (ciz + R < GRID - 1) g = fminf(g, (float)(ciz + R + 1) * HCELL - piz);
        float d10 = __uint_as_float((unsigned)(d10key >> 32));
        if (d10 < g * g) break;   // NaN d10 (未filled) -> false -> expand
    }

    // reduce density + covariance across the 8 lanes
#pragma unroll
    for (int o = 1; o < 8; o <<= 1) {
        cnt += __shfl_xor_sync(0xFFFFFFFFu, cnt, o);
        c00 += __shfl_xor_sync(0xFFFFFFFFu, c00, o);
        c01 += __shfl_xor_sync(0xFFFFFFFFu, c01, o);
        c02 += __shfl_xor_sync(0xFFFFFFFFu, c02, o);
        c11 += __shfl_xor_sync(0xFFFFFFFFu, c11, o);
        c12 += __shfl_xor_sync(0xFFFFFFFFu, c12, o);
        c22 += __shfl_xor_sync(0xFFFFFFFFu, c22, o);
    }

    if (l8 == 0) {
        c00 = __fdiv_rn(c00, 10.0f); c01 = __fdiv_rn(c01, 10.0f); c02 = __fdiv_rn(c02, 10.0f);
        c11 = __fdiv_rn(c11, 10.0f); c12 = __fdiv_rn(c12, 10.0f); c22 = __fdiv_rn(c22, 10.0f);
        float curv = curv_from_cov(c00, c01, c02, c11, c12, c22);

        double cm   = g_cacc[b][3];
        double cden = cm > 1.0 ? cm : 1.0;
        float cx = (float)(g_cacc[b][0] / cden);
        float cy = (float)(g_cacc[b][1] / cden);
        float cz = (float)(g_cacc[b][2] / cden);
        float rx = pix - cx, ry = piy - cy, rz = piz - cz;
        float distc = __fsqrt_rn(__fadd_rn(__fadd_rn(__fmul_rn(rx, rx), __fmul_rn(ry, ry)), __fmul_rn(rz, rz)));
        float horiz = __fsqrt_rn(__fadd_rn(__fmul_rn(rx, rx), __fmul_rn(ry, ry)));
        float rad   = atan2f(ry, rx);

        bool valid = cm > 0.0;
        g_geom[orig * 6 + 0] = valid ? distc : 0.0f;
        g_geom[orig * 6 + 1] = valid ? rz    : 0.0f;
        g_geom[orig * 6 + 2] = valid ? horiz : 0.0f;
        g_geom[orig * 6 + 3] = valid ? (float)cnt : 0.0f;
        g_geom[orig * 6 + 4] = valid ? curv  : 0.0f;
        g_geom[orig * 6 + 5] = valid ? rad   : 0.0f;
    }
}

// ---------------- fused 2-layer MLP with f32x2 FMA ----------------
__global__ void __launch_bounds__(256) k_mlp(const float* __restrict__ feat,
                                             const float* __restrict__ W1,
                                             const float* __restrict__ b1,
                                             const float* __restrict__ W2,
                                             const float* __restrict__ b2,
                                             float* __restrict__ out) {
    extern __shared__ float sm[];
    float* sW1 = sm;             // 70*128
    float* sB1 = sm + 8960;
    float* sW2 = sm + 9088;      // 128*128
    float* sB2 = sm + 25472;
    float* sX  = sm + 25600;     // 128*72
    float* sH  = sm + 34816;     // 128*132

    int tid = threadIdx.x;
    for (int i = tid; i < 8960;  i += 256) sW1[i] = W1[i];
    for (int i = tid; i < 16384; i += 256) sW2[i] = W2[i];
    if (tid < 128) { sB1[tid] = b1[tid]; sB2[tid] = b2[tid]; }

    int m0 = blockIdx.x * 128;
    for (int i = tid; i < 128 * 64; i += 256) {
        int r = i >> 6, c = i & 63;
        sX[r * 72 + c] = feat[(m0 + r) * 64 + c];
    }
    for (int i = tid; i < 128 * 6; i += 256) {
        int r = i / 6, c = i % 6;
        sX[r * 72 + 64 + c] = g_geom[(m0 + r) * 6 + c];
    }
    __syncthreads();

    int cg = tid & 31;
    int rg = tid >> 5;

    unsigned long long acc[16][2];
#pragma unroll
    for (int r = 0; r < 16; r++) { acc[r][0] = 0ull; acc[r][1] = 0ull; }

    for (int k = 0; k < 70; k++) {
        ulonglong2 w2 = *(const ulonglong2*)(sW1 + k * 128 + cg * 4);
#pragma unroll
        for (int r = 0; r < 16; r++) {
            unsigned long long xp = pack2(sX[(rg * 16 + r) * 72 + k]);
            FMA2(acc[r][0], w2.x, xp);
            FMA2(acc[r][1], w2.y, xp);
        }
    }
    {
        float4 bv = *(const float4*)(sB1 + cg * 4);
#pragma unroll
        for (int r = 0; r < 16; r++) {
            float a0, a1, a2, a3;
            unpack2(acc[r][0], a0, a1);
            unpack2(acc[r][1], a2, a3);
            float4 h;
            h.x = fmaxf(a0 + bv.x, 0.0f);
            h.y = fmaxf(a1 + bv.y, 0.0f);
            h.z = fmaxf(a2 + bv.z, 0.0f);
            h.w = fmaxf(a3 + bv.w, 0.0f);
            *(float4*)(sH + (rg * 16 + r) * 132 + cg * 4) = h;
        }
    }
    __syncthreads();

#pragma unroll
    for (int r = 0; r < 16; r++) { acc[r][0] = 0ull; acc[r][1] = 0ull; }

    for (int k = 0; k < 128; k++) {
        ulonglong2 w2 = *(const ulonglong2*)(sW2 + k * 128 + cg * 4);
#pragma unroll
        for (int r = 0; r < 16; r++) {
            unsigned long long hp = pack2(sH[(rg * 16 + r) * 132 + k]);
            FMA2(acc[r][0], w2.x, hp);
            FMA2(acc[r][1], w2.y, hp);
        }
    }
    {
        float4 bv = *(const float4*)(sB2 + cg * 4);
#pragma unroll
        for (int r = 0; r < 16; r++) {
            float a0, a1, a2, a3;
            unpack2(acc[r][0], a0, a1);
            unpack2(acc[r][1], a2, a3);
            float4 o;
            o.x = fmaxf(a0 + bv.x, 0.0f);
            o.y = fmaxf(a1 + bv.y, 0.0f);
            o.z = fmaxf(a2 + bv.z, 0.0f);
            o.w = fmaxf(a3 + bv.w, 0.0f);
            *(float4*)(out + (size_t)(m0 + rg * 16 + r) * 128 + cg * 4) = o;
        }
    }
}

// ---------------- launch ----------------
extern "C" void kernel_launch(void* const* d_in, const int* in_sizes, int n_in,
                              void* d_out, int out_size) {
    const float* points = (const float*)d_in[0];
    const float* feat   = (const float*)d_in[1];
    const void*  mask   = d_in[2];
    const float* W1     = (const float*)d_in[3];
    const float* b1     = (const float*)d_in[4];
    const float* W2     = (const float*)d_in[5];
    const float* b2     = (const float*)d_in[6];
    float* out = (float*)d_out;

    cudaFuncSetAttribute(k_mlp, cudaFuncAttributeMaxDynamicSharedMemorySize, 212992);

    k_init   <<<(BB * GC + 255) / 256, 256>>>();
    k_count  <<<(NPT + 255) / 256, 256>>>(points, (const unsigned char*)mask);
    k_scan   <<<BB, 256>>>();
    k_scatter<<<(NPT + 255) / 256, 256>>>(points, mask);
    k_geom   <<<(NPT * 8) / 256, 256>>>();
    k_mlp    <<<NPT / 128, 256, 206848>>>(feat, W1, b1, W2, b2, out);
}